// round 14
// baseline (speedup 1.0000x reference)
#include <cuda_runtime.h>
#include <cuda_fp16.h>
#include <math.h>
#include <stdint.h>

// MedicalMoE on GB300 (plain sm_103 target).
// gate fp32 -> dispatch -> pure fp16 mma.sync expert GEMMs.
// Round 14: KCH=64 (half the barriers), single __syncthreads per chunk
// (3-stage ring, distance-2 prefetch), B fragments via ldmatrix.x4.trans.
#define BT 16384
#define DM 1024
#define HE 4096
#define NE 8
#define TK 2
#define GHD 256
#define NROWS (BT * TK)
#define MAXROWS_PER_E BT

// ------------------------- device scratch -------------------------
__device__ float g_hidden[(size_t)BT * GHD];
__device__ int   g_counts[NE];
__device__ int   g_starts[NE];
__device__ int   g_fill[NE];
__device__ int   g_eid[NROWS];
__device__ float g_ew[NROWS];
__device__ int   g_rowmap[NROWS];
__device__ float g_roww[NROWS];
__device__ __half g_x16[(size_t)BT * DM];
__device__ __half g_w1[(size_t)NE * DM * HE];  // [E][K][N] fp16
__device__ __half g_w2[(size_t)NE * HE * DM];  // [E][K][N] fp16
__device__ __half g_h16[(size_t)NROWS * HE];

// ------------------------- PTX helpers -------------------------
__device__ __forceinline__ uint32_t smem_to_u32(const void* p) {
    uint32_t a;
    asm("{ .reg .u64 t; cvta.to.shared.u64 t, %1; cvt.u32.u64 %0, t; }" : "=r"(a) : "l"(p));
    return a;
}
#define CP_ASYNC16(saddr, gptr) \
    asm volatile("cp.async.cg.shared.global [%0], [%1], 16;" :: "r"(saddr), "l"(gptr) : "memory")
#define CP_COMMIT() asm volatile("cp.async.commit_group;" ::: "memory")
#define CP_WAIT(n)  asm volatile("cp.async.wait_group %0;" :: "n"(n) : "memory")
#define LDMATRIX_X4(r0,r1,r2,r3, addr) \
    asm volatile("ldmatrix.sync.aligned.m8n8.x4.shared.b16 {%0,%1,%2,%3}, [%4];" \
        : "=r"(r0),"=r"(r1),"=r"(r2),"=r"(r3) : "r"(addr) : "memory")
#define LDMATRIX_X4T(r0,r1,r2,r3, addr) \
    asm volatile("ldmatrix.sync.aligned.m8n8.x4.trans.shared.b16 {%0,%1,%2,%3}, [%4];" \
        : "=r"(r0),"=r"(r1),"=r"(r2),"=r"(r3) : "r"(addr) : "memory")
#define MMA16816(d, a, b0, b1) \
    asm volatile("mma.sync.aligned.m16n8k16.row.col.f32.f16.f16.f32 " \
        "{%0,%1,%2,%3}, {%4,%5,%6,%7}, {%8,%9}, {%0,%1,%2,%3};" \
        : "+f"((d)[0]),"+f"((d)[1]),"+f"((d)[2]),"+f"((d)[3]) \
        : "r"((a)[0]),"r"((a)[1]),"r"((a)[2]),"r"((a)[3]),"r"(b0),"r"(b1))

// ------------------------- setup kernels -------------------------
__global__ void k_init() { if (threadIdx.x < NE) g_counts[threadIdx.x] = 0; }

__global__ void k_scan() {
    int s = 0;
    for (int e = 0; e < NE; e++) { g_starts[e] = s; s += g_counts[e]; g_fill[e] = 0; }
}

__global__ void k_scatter() {
    int t = blockIdx.x * blockDim.x + threadIdx.x;
    if (t >= BT) return;
#pragma unroll
    for (int k = 0; k < TK; k++) {
        int e = g_eid[t * TK + k];
        int pos = g_starts[e] + atomicAdd(&g_fill[e], 1);
        g_rowmap[pos] = t;
        g_roww[pos] = g_ew[t * TK + k];
    }
}

// x -> fp16
__global__ __launch_bounds__(256) void k_xsplit(const float* __restrict__ x) {
    size_t i = ((size_t)blockIdx.x * 256 + threadIdx.x) * 4;
    float4 v = *(const float4*)(x + i);
    __half h0 = __float2half(v.x), h1 = __float2half(v.y);
    __half h2 = __float2half(v.z), h3 = __float2half(v.w);
    uint2 p;
    p.x = ((uint32_t)__half_as_ushort(h1) << 16) | __half_as_ushort(h0);
    p.y = ((uint32_t)__half_as_ushort(h3) << 16) | __half_as_ushort(h2);
    *(uint2*)(g_x16 + i) = p;
}

// weights -> fp16 (destinations selected in device code only)
template <int W2>
__global__ __launch_bounds__(256) void k_wconv(const float* __restrict__ W)
{
    size_t i = ((size_t)blockIdx.x * 256 + threadIdx.x) * 4;
    float4 v = *(const float4*)(W + i);
    __half h0 = __float2half(v.x), h1 = __float2half(v.y);
    __half h2 = __float2half(v.z), h3 = __float2half(v.w);
    uint2 p;
    p.x = ((uint32_t)__half_as_ushort(h1) << 16) | __half_as_ushort(h0);
    p.y = ((uint32_t)__half_as_ushort(h3) << 16) | __half_as_ushort(h2);
    if (W2) *(uint2*)(g_w2 + i) = p;
    else    *(uint2*)(g_w1 + i) = p;
}

// ------------------------- gating (fp32, proven) -------------------------
__global__ __launch_bounds__(256) void k_gate_gemm(
    const float* __restrict__ X, const float* __restrict__ W, const float* __restrict__ bias)
{
    const int K = DM, N = GHD;
    __shared__ float As[8][128];
    __shared__ float Bs[8][128];
    int tid = threadIdx.x;
    int row0 = blockIdx.y * 128, col0 = blockIdx.x * 128;
    int arow = tid >> 1, acol = (tid & 1) * 4;
    int brow = tid >> 5, bcol = (tid & 31) * 4;
    int tx = tid & 15, ty = tid >> 4;
    float acc[8][8];
#pragma unroll
    for (int i = 0; i < 8; i++)
#pragma unroll
        for (int j = 0; j < 8; j++) acc[i][j] = 0.f;
    const float* Aptr = X + (size_t)(row0 + arow) * K + acol;
    const float* Bptr = W + (size_t)brow * N + col0 + bcol;
    for (int k0 = 0; k0 < K; k0 += 8) {
        float4 av = *(const float4*)(Aptr + k0);
        As[acol + 0][arow] = av.x; As[acol + 1][arow] = av.y;
        As[acol + 2][arow] = av.z; As[acol + 3][arow] = av.w;
        *(float4*)&Bs[brow][bcol] = *(const float4*)(Bptr + (size_t)k0 * N);
        __syncthreads();
#pragma unroll
        for (int kk = 0; kk < 8; kk++) {
            float a[8], b[8];
            float4 t0 = *(const float4*)&As[kk][ty * 4];
            float4 t1 = *(const float4*)&As[kk][64 + ty * 4];
            a[0]=t0.x;a[1]=t0.y;a[2]=t0.z;a[3]=t0.w;a[4]=t1.x;a[5]=t1.y;a[6]=t1.z;a[7]=t1.w;
            float4 u0 = *(const float4*)&Bs[kk][tx * 4];
            float4 u1 = *(const float4*)&Bs[kk][64 + tx * 4];
            b[0]=u0.x;b[1]=u0.y;b[2]=u0.z;b[3]=u0.w;b[4]=u1.x;b[5]=u1.y;b[6]=u1.z;b[7]=u1.w;
#pragma unroll
            for (int i = 0; i < 8; i++)
#pragma unroll
                for (int j = 0; j < 8; j++) acc[i][j] += a[i] * b[j];
        }
        __syncthreads();
    }
#pragma unroll
    for (int i = 0; i < 8; i++) {
        int r = row0 + ((i < 4) ? (ty * 4 + i) : (64 + ty * 4 + (i - 4)));
#pragma unroll
        for (int j = 0; j < 8; j++) {
            int c = col0 + ((j < 4) ? (tx * 4 + j) : (64 + tx * 4 + (j - 4)));
            float v = acc[i][j] + bias[c];
            g_hidden[(size_t)r * GHD + c] = v > 0.f ? v : 0.f;
        }
    }
}

__global__ __launch_bounds__(256) void k_gate2(
    const float* __restrict__ gw2, const float* __restrict__ gb2, float* tail)
{
    __shared__ float sW[GHD * NE];
    __shared__ float sb[NE];
    int tid = threadIdx.x;
    for (int i = tid; i < GHD * NE; i += 256) sW[i] = gw2[i];
    if (tid < NE) sb[tid] = gb2[tid];
    __syncthreads();
    int warp = tid >> 5, lane = tid & 31;
    int token = blockIdx.x * 8 + warp;
    const float* hrow = g_hidden + (size_t)token * GHD;
    float l[NE];
#pragma unroll
    for (int e = 0; e < NE; e++) l[e] = 0.f;
#pragma unroll
    for (int i = 0; i < GHD / 32; i++) {
        int r = lane + i * 32;
        float hv = hrow[r];
#pragma unroll
        for (int e = 0; e < NE; e++) l[e] += hv * sW[r * NE + e];
    }
#pragma unroll
    for (int off = 16; off > 0; off >>= 1)
#pragma unroll
        for (int e = 0; e < NE; e++) l[e] += __shfl_down_sync(0xffffffffu, l[e], off);
    if (lane == 0) {
        float p[NE]; float m = -1e30f;
#pragma unroll
        for (int e = 0; e < NE; e++) { l[e] += sb[e]; m = fmaxf(m, l[e]); }
        float s = 0.f;
#pragma unroll
        for (int e = 0; e < NE; e++) { p[e] = expf(l[e] - m); s += p[e]; }
        float inv = 1.f / s;
#pragma unroll
        for (int e = 0; e < NE; e++) p[e] *= inv;
        int b0 = 0; float v0 = p[0];
#pragma unroll
        for (int e = 1; e < NE; e++) if (p[e] > v0) { v0 = p[e]; b0 = e; }
        int b1 = -1; float v1 = -1e30f;
#pragma unroll
        for (int e = 0; e < NE; e++) if (e != b0 && p[e] > v1) { v1 = p[e]; b1 = e; }
        float d = 1.f / (v0 + v1);
        g_eid[token * TK + 0] = b0; g_ew[token * TK + 0] = v0 * d;
        g_eid[token * TK + 1] = b1; g_ew[token * TK + 1] = v1 * d;
        atomicAdd(&g_counts[b0], 1);
        atomicAdd(&g_counts[b1], 1);
        if (tail) { tail[token * TK + 0] = (float)b0; tail[token * TK + 1] = (float)b1; }
    }
}

// ------------------------- pure fp16 mma.sync grouped GEMM ------------------------
// CTA tile 128(M) x 128(N), K-chunk 64, 3-stage cp.async (distance 2), 2 CTAs/SM.
// Warp tile 64M x 32N (8 warps = 2M x 4N). One __syncthreads per chunk.
#define KCH 64
#define A_STRIDE 144           // (64+8)*2 bytes per m-row
#define B_STRIDE 272           // (128+8)*2 bytes per k-row
#define A_TILE (128 * A_STRIDE)        // 18432
#define B_TILE (KCH * B_STRIDE)        // 17408
#define OFF_A  0
#define OFF_B  A_TILE
#define STAGE_SZ (A_TILE + B_TILE)         // 35840
#define NSTAGE 3
#define SMEM_MMA (NSTAGE * STAGE_SZ)       // 107520 (x2 CTAs = 215040 <= 228KB)

// MODE 0: GEMM1 (A = gathered x fp16, epilogue tanh -> g_h16)
// MODE 1: GEMM2 (A = contiguous h rows, epilogue weighted atomicAdd -> out)
template <int KDIM, int NDIM, int MODE>
__global__ __launch_bounds__(256, 2) void k_moe_mma(const float* __restrict__ bias,
                                                    float* __restrict__ out)
{
    int e = blockIdx.z;
    int rows = g_counts[e];
    int base = g_starts[e];
    int row0 = blockIdx.y * 128;
    if (row0 >= rows) return;
    int col0 = blockIdx.x * 128;

    extern __shared__ char smem[];
    uint32_t sb = smem_to_u32(smem);
    int tid = threadIdx.x, wid = tid >> 5, lane = tid & 31;

    // ---- global load mapping ----
    // A: 2 threads/row, 4 x 16B each (64 k).  B: 4 threads/k-row, 4 x 16B each.
    int am_row = tid >> 1, a_hf = tid & 1;
    int bk_row = tid >> 2, b_sg = tid & 3;

    const __half* AP;
    size_t aoff;
    int arc = (row0 + am_row < rows) ? (row0 + am_row) : (rows - 1);
    if (MODE == 0) {
        AP = g_x16;
        aoff = (size_t)g_rowmap[base + arc] * KDIM;
    } else {
        AP = g_h16;
        aoff = (size_t)(base + arc) * KDIM;
    }
    const __half* BP = (MODE == 0 ? g_w1 : g_w2) + (size_t)e * KDIM * NDIM;

    uint32_t sA = sb + OFF_A + am_row * A_STRIDE + a_hf * 64;
    uint32_t sB = sb + OFF_B + bk_row * B_STRIDE + b_sg * 64;

    auto load_chunk = [&](int stage, int kc) {
        uint32_t bb = stage * STAGE_SZ;
        const __half* ga = AP + aoff + kc * KCH + a_hf * 32;
#pragma unroll
        for (int j = 0; j < 4; j++)
            CP_ASYNC16(sA + bb + j * 16, ga + j * 8);
        const __half* gb = BP + (size_t)(kc * KCH + bk_row) * NDIM + col0 + b_sg * 32;
#pragma unroll
        for (int j = 0; j < 4; j++)
            CP_ASYNC16(sB + bb + j * 16, gb + j * 8);
        CP_COMMIT();
    };

    // ---- ldmatrix fragment addresses (warp tile 64M x 32N; 8 warps = 2M x 4N) ----
    int warp_m = wid & 1, warp_n = wid >> 1;
    uint32_t aAddr0 = sb + OFF_A + (warp_m * 64 + (lane & 15)) * A_STRIDE + ((lane >> 4) & 1) * 16;
    uint32_t bAddr0 = sb + OFF_B + (lane & 15) * B_STRIDE + ((lane >> 4) & 1) * 16 + warp_n * 64;

    float acc[4][4][4];
#pragma unroll
    for (int mf = 0; mf < 4; mf++)
#pragma unroll
        for (int nf = 0; nf < 4; nf++)
#pragma unroll
            for (int q = 0; q < 4; q++) acc[mf][nf][q] = 0.f;

    const int NK = KDIM / KCH;
    load_chunk(0, 0);
    load_chunk(1, 1);

    for (int kc = 0; kc < NK; kc++) {
        if (kc + 1 < NK) CP_WAIT(1); else CP_WAIT(0);
        __syncthreads();
        uint32_t bb = (kc % NSTAGE) * STAGE_SZ;
#pragma unroll
        for (int ks = 0; ks < 4; ks++) {
            uint32_t a_r[4][4];
#pragma unroll
            for (int mf = 0; mf < 4; mf++) {
                uint32_t ad = aAddr0 + bb + mf * 16 * A_STRIDE + ks * 32;
                LDMATRIX_X4(a_r[mf][0], a_r[mf][1], a_r[mf][2], a_r[mf][3], ad);
            }
#pragma unroll
            for (int np = 0; np < 2; np++) {
                uint32_t bd = bAddr0 + bb + ks * 16 * B_STRIDE + np * 32;
                uint32_t b0, b1, b2, b3;
                LDMATRIX_X4T(b0, b1, b2, b3, bd);
#pragma unroll
                for (int mf = 0; mf < 4; mf++) {
                    MMA16816(acc[mf][2 * np + 0], a_r[mf], b0, b1);
                    MMA16816(acc[mf][2 * np + 1], a_r[mf], b2, b3);
                }
            }
        }
        if (kc + 2 < NK) load_chunk((kc + 2) % NSTAGE, kc + 2);
    }

    // ---- epilogue (register accumulators) ----
    int rb = row0 + warp_m * 64 + (lane >> 2);
    int cb = col0 + warp_n * 32 + (lane & 3) * 2;
    const float* bp = bias + (size_t)e * NDIM;
#pragma unroll
    for (int mf = 0; mf < 4; mf++) {
#pragma unroll
        for (int half2 = 0; half2 < 2; half2++) {
            int r = rb + mf * 16 + half2 * 8;
            if (r >= rows) continue;
            size_t orow; float wgt = 1.f;
            if (MODE == 0) {
                orow = (size_t)(base + r) * NDIM;
            } else {
                int pos = base + r;
                orow = (size_t)g_rowmap[pos] * NDIM;
                wgt = g_roww[pos];
            }
#pragma unroll
            for (int nf = 0; nf < 4; nf++) {
                int c = cb + nf * 8;
                float v0 = acc[mf][nf][half2 * 2 + 0] + bp[c];
                float v1 = acc[mf][nf][half2 * 2 + 1] + bp[c + 1];
                if (MODE == 0) {
                    __half t0 = __float2half(tanhf(v0));
                    __half t1 = __float2half(tanhf(v1));
                    uint32_t ph = ((uint32_t)__half_as_ushort(t1) << 16) | __half_as_ushort(t0);
                    *(uint32_t*)(g_h16 + orow + c) = ph;
                } else {
                    atomicAdd(out + orow + c, v0 * wgt);
                    atomicAdd(out + orow + c + 1, v1 * wgt);
                }
            }
        }
    }
}

// ------------------------- launch -------------------------
extern "C" void kernel_launch(void* const* d_in, const int* in_sizes, int n_in,
                              void* d_out, int out_size)
{
    const float* x   = (const float*)d_in[0];
    const float* gw1 = (const float*)d_in[1];
    const float* gb1 = (const float*)d_in[2];
    const float* gw2 = (const float*)d_in[3];
    const float* gb2 = (const float*)d_in[4];
    const float* ew1 = (const float*)d_in[5];
    const float* eb1 = (const float*)d_in[6];
    const float* ew2 = (const float*)d_in[7];
    const float* eb2 = (const float*)d_in[8];
    float* out = (float*)d_out;

    cudaFuncSetAttribute(k_moe_mma<DM, HE, 0>, cudaFuncAttributeMaxDynamicSharedMemorySize, SMEM_MMA);
    cudaFuncSetAttribute(k_moe_mma<HE, DM, 1>, cudaFuncAttributeMaxDynamicSharedMemorySize, SMEM_MMA);

    cudaMemsetAsync(d_out, 0, (size_t)out_size * sizeof(float));
    k_init<<<1, 32>>>();

    // precision conversions
    k_xsplit<<<(BT * DM) / 1024, 256>>>(x);
    k_wconv<0><<<(NE * DM * HE) / 1024, 256>>>(ew1);
    k_wconv<1><<<(NE * HE * DM) / 1024, 256>>>(ew2);

    // gating
    dim3 gg(GHD / 128, BT / 128);
    k_gate_gemm<<<gg, 256>>>(x, gw1, gb1);
    long long extra = (long long)out_size - (long long)BT * DM;
    float* tail = (extra >= (long long)BT * TK) ? (out + (size_t)BT * DM) : nullptr;
    k_gate2<<<BT / 8, 256>>>(gw2, gb2, tail);
    k_scan<<<1, 1>>>();
    k_scatter<<<BT / 256, 256>>>();

    // expert GEMMs (pure fp16 HMMA, KCH=64, 3-stage, 2 CTAs/SM)
    dim3 ge1(HE / 128, MAXROWS_PER_E / 128, NE);
    k_moe_mma<DM, HE, 0><<<ge1, 256, SMEM_MMA>>>(eb1, nullptr);
    dim3 ge2(DM / 128, MAXROWS_PER_E / 128, NE);
    k_moe_mma<HE, DM, 1><<<ge2, 256, SMEM_MMA>>>(eb2, out);
}

// round 15
// speedup vs baseline: 1.0472x; 1.0472x over previous
#include <cuda_runtime.h>
#include <cuda_fp16.h>
#include <math.h>
#include <stdint.h>

// MedicalMoE on GB300 (plain sm_103 target).
// gate fp32 -> dispatch -> pure fp16 mma.sync expert GEMMs (round-13 engine).
// Round 15: GEMM2 epilogue writes weighted partials to g_y (plain stores,
// no atomics); k_combine sums the 2 partials per token. NSTAGE 4->5.
#define BT 16384
#define DM 1024
#define HE 4096
#define NE 8
#define TK 2
#define GHD 256
#define NROWS (BT * TK)
#define MAXROWS_PER_E BT

// ------------------------- device scratch -------------------------
__device__ float g_hidden[(size_t)BT * GHD];
__device__ int   g_counts[NE];
__device__ int   g_starts[NE];
__device__ int   g_fill[NE];
__device__ int   g_eid[NROWS];
__device__ float g_ew[NROWS];
__device__ int   g_rowmap[NROWS];
__device__ float g_roww[NROWS];
__device__ int   g_postok[NROWS];              // token -> its 2 positions
__device__ __half g_x16[(size_t)BT * DM];
__device__ __half g_w1[(size_t)NE * DM * HE];  // [E][K][N] fp16
__device__ __half g_w2[(size_t)NE * HE * DM];  // [E][K][N] fp16
__device__ __half g_h16[(size_t)NROWS * HE];
__device__ float  g_y[(size_t)NROWS * DM];     // weighted GEMM2 partials

// ------------------------- PTX helpers -------------------------
__device__ __forceinline__ uint32_t smem_to_u32(const void* p) {
    uint32_t a;
    asm("{ .reg .u64 t; cvta.to.shared.u64 t, %1; cvt.u32.u64 %0, t; }" : "=r"(a) : "l"(p));
    return a;
}
#define CP_ASYNC16(saddr, gptr) \
    asm volatile("cp.async.cg.shared.global [%0], [%1], 16;" :: "r"(saddr), "l"(gptr) : "memory")
#define CP_COMMIT() asm volatile("cp.async.commit_group;" ::: "memory")
#define CP_WAIT(n)  asm volatile("cp.async.wait_group %0;" :: "n"(n) : "memory")
#define LDMATRIX_X4(r0,r1,r2,r3, addr) \
    asm volatile("ldmatrix.sync.aligned.m8n8.x4.shared.b16 {%0,%1,%2,%3}, [%4];" \
        : "=r"(r0),"=r"(r1),"=r"(r2),"=r"(r3) : "r"(addr) : "memory")
#define LDMATRIX_X2T(r0,r1, addr) \
    asm volatile("ldmatrix.sync.aligned.m8n8.x2.trans.shared.b16 {%0,%1}, [%2];" \
        : "=r"(r0),"=r"(r1) : "r"(addr) : "memory")
#define MMA16816(d, a, b) \
    asm volatile("mma.sync.aligned.m16n8k16.row.col.f32.f16.f16.f32 " \
        "{%0,%1,%2,%3}, {%4,%5,%6,%7}, {%8,%9}, {%0,%1,%2,%3};" \
        : "+f"((d)[0]),"+f"((d)[1]),"+f"((d)[2]),"+f"((d)[3]) \
        : "r"((a)[0]),"r"((a)[1]),"r"((a)[2]),"r"((a)[3]),"r"((b)[0]),"r"((b)[1]))

// ------------------------- setup kernels -------------------------
__global__ void k_init() { if (threadIdx.x < NE) g_counts[threadIdx.x] = 0; }

__global__ void k_scan() {
    int s = 0;
    for (int e = 0; e < NE; e++) { g_starts[e] = s; s += g_counts[e]; g_fill[e] = 0; }
}

__global__ void k_scatter() {
    int t = blockIdx.x * blockDim.x + threadIdx.x;
    if (t >= BT) return;
#pragma unroll
    for (int k = 0; k < TK; k++) {
        int e = g_eid[t * TK + k];
        int pos = g_starts[e] + atomicAdd(&g_fill[e], 1);
        g_rowmap[pos] = t;
        g_roww[pos] = g_ew[t * TK + k];
        g_postok[t * TK + k] = pos;
    }
}

// out[t] = y[pos0(t)] + y[pos1(t)]   (float4 vectorized)
__global__ __launch_bounds__(256) void k_combine(float* __restrict__ out)
{
    size_t i = (size_t)blockIdx.x * 256 + threadIdx.x;   // over BT*DM/4
    int t = (int)(i / (DM / 4));
    int off = (int)(i % (DM / 4)) * 4;
    int p0 = g_postok[t * TK + 0];
    int p1 = g_postok[t * TK + 1];
    float4 a = *(const float4*)(g_y + (size_t)p0 * DM + off);
    float4 b = *(const float4*)(g_y + (size_t)p1 * DM + off);
    float4 r;
    r.x = a.x + b.x; r.y = a.y + b.y; r.z = a.z + b.z; r.w = a.w + b.w;
    *(float4*)(out + (size_t)t * DM + off) = r;
}

// x -> fp16
__global__ __launch_bounds__(256) void k_xsplit(const float* __restrict__ x) {
    size_t i = ((size_t)blockIdx.x * 256 + threadIdx.x) * 4;
    float4 v = *(const float4*)(x + i);
    __half h0 = __float2half(v.x), h1 = __float2half(v.y);
    __half h2 = __float2half(v.z), h3 = __float2half(v.w);
    uint2 p;
    p.x = ((uint32_t)__half_as_ushort(h1) << 16) | __half_as_ushort(h0);
    p.y = ((uint32_t)__half_as_ushort(h3) << 16) | __half_as_ushort(h2);
    *(uint2*)(g_x16 + i) = p;
}

// weights -> fp16 (destinations selected in device code only)
template <int W2>
__global__ __launch_bounds__(256) void k_wconv(const float* __restrict__ W)
{
    size_t i = ((size_t)blockIdx.x * 256 + threadIdx.x) * 4;
    float4 v = *(const float4*)(W + i);
    __half h0 = __float2half(v.x), h1 = __float2half(v.y);
    __half h2 = __float2half(v.z), h3 = __float2half(v.w);
    uint2 p;
    p.x = ((uint32_t)__half_as_ushort(h1) << 16) | __half_as_ushort(h0);
    p.y = ((uint32_t)__half_as_ushort(h3) << 16) | __half_as_ushort(h2);
    if (W2) *(uint2*)(g_w2 + i) = p;
    else    *(uint2*)(g_w1 + i) = p;
}

// ------------------------- gating (fp32, proven) -------------------------
__global__ __launch_bounds__(256) void k_gate_gemm(
    const float* __restrict__ X, const float* __restrict__ W, const float* __restrict__ bias)
{
    const int K = DM, N = GHD;
    __shared__ float As[8][128];
    __shared__ float Bs[8][128];
    int tid = threadIdx.x;
    int row0 = blockIdx.y * 128, col0 = blockIdx.x * 128;
    int arow = tid >> 1, acol = (tid & 1) * 4;
    int brow = tid >> 5, bcol = (tid & 31) * 4;
    int tx = tid & 15, ty = tid >> 4;
    float acc[8][8];
#pragma unroll
    for (int i = 0; i < 8; i++)
#pragma unroll
        for (int j = 0; j < 8; j++) acc[i][j] = 0.f;
    const float* Aptr = X + (size_t)(row0 + arow) * K + acol;
    const float* Bptr = W + (size_t)brow * N + col0 + bcol;
    for (int k0 = 0; k0 < K; k0 += 8) {
        float4 av = *(const float4*)(Aptr + k0);
        As[acol + 0][arow] = av.x; As[acol + 1][arow] = av.y;
        As[acol + 2][arow] = av.z; As[acol + 3][arow] = av.w;
        *(float4*)&Bs[brow][bcol] = *(const float4*)(Bptr + (size_t)k0 * N);
        __syncthreads();
#pragma unroll
        for (int kk = 0; kk < 8; kk++) {
            float a[8], b[8];
            float4 t0 = *(const float4*)&As[kk][ty * 4];
            float4 t1 = *(const float4*)&As[kk][64 + ty * 4];
            a[0]=t0.x;a[1]=t0.y;a[2]=t0.z;a[3]=t0.w;a[4]=t1.x;a[5]=t1.y;a[6]=t1.z;a[7]=t1.w;
            float4 u0 = *(const float4*)&Bs[kk][tx * 4];
            float4 u1 = *(const float4*)&Bs[kk][64 + tx * 4];
            b[0]=u0.x;b[1]=u0.y;b[2]=u0.z;b[3]=u0.w;b[4]=u1.x;b[5]=u1.y;b[6]=u1.z;b[7]=u1.w;
#pragma unroll
            for (int i = 0; i < 8; i++)
#pragma unroll
                for (int j = 0; j < 8; j++) acc[i][j] += a[i] * b[j];
        }
        __syncthreads();
    }
#pragma unroll
    for (int i = 0; i < 8; i++) {
        int r = row0 + ((i < 4) ? (ty * 4 + i) : (64 + ty * 4 + (i - 4)));
#pragma unroll
        for (int j = 0; j < 8; j++) {
            int c = col0 + ((j < 4) ? (tx * 4 + j) : (64 + tx * 4 + (j - 4)));
            float v = acc[i][j] + bias[c];
            g_hidden[(size_t)r * GHD + c] = v > 0.f ? v : 0.f;
        }
    }
}

__global__ __launch_bounds__(256) void k_gate2(
    const float* __restrict__ gw2, const float* __restrict__ gb2, float* tail)
{
    __shared__ float sW[GHD * NE];
    __shared__ float sb[NE];
    int tid = threadIdx.x;
    for (int i = tid; i < GHD * NE; i += 256) sW[i] = gw2[i];
    if (tid < NE) sb[tid] = gb2[tid];
    __syncthreads();
    int warp = tid >> 5, lane = tid & 31;
    int token = blockIdx.x * 8 + warp;
    const float* hrow = g_hidden + (size_t)token * GHD;
    float l[NE];
#pragma unroll
    for (int e = 0; e < NE; e++) l[e] = 0.f;
#pragma unroll
    for (int i = 0; i < GHD / 32; i++) {
        int r = lane + i * 32;
        float hv = hrow[r];
#pragma unroll
        for (int e = 0; e < NE; e++) l[e] += hv * sW[r * NE + e];
    }
#pragma unroll
    for (int off = 16; off > 0; off >>= 1)
#pragma unroll
        for (int e = 0; e < NE; e++) l[e] += __shfl_down_sync(0xffffffffu, l[e], off);
    if (lane == 0) {
        float p[NE]; float m = -1e30f;
#pragma unroll
        for (int e = 0; e < NE; e++) { l[e] += sb[e]; m = fmaxf(m, l[e]); }
        float s = 0.f;
#pragma unroll
        for (int e = 0; e < NE; e++) { p[e] = expf(l[e] - m); s += p[e]; }
        float inv = 1.f / s;
#pragma unroll
        for (int e = 0; e < NE; e++) p[e] *= inv;
        int b0 = 0; float v0 = p[0];
#pragma unroll
        for (int e = 1; e < NE; e++) if (p[e] > v0) { v0 = p[e]; b0 = e; }
        int b1 = -1; float v1 = -1e30f;
#pragma unroll
        for (int e = 0; e < NE; e++) if (e != b0 && p[e] > v1) { v1 = p[e]; b1 = e; }
        float d = 1.f / (v0 + v1);
        g_eid[token * TK + 0] = b0; g_ew[token * TK + 0] = v0 * d;
        g_eid[token * TK + 1] = b1; g_ew[token * TK + 1] = v1 * d;
        atomicAdd(&g_counts[b0], 1);
        atomicAdd(&g_counts[b1], 1);
        if (tail) { tail[token * TK + 0] = (float)b0; tail[token * TK + 1] = (float)b1; }
    }
}

// ------------------------- pure fp16 mma.sync grouped GEMM ------------------------
// CTA tile 128(M) x 128(N), K-chunk 32, 5-stage cp.async, 2 CTAs/SM.
// Warp tile 64M x 32N (8 warps = 2M x 4N).
#define KCH 32
#define A_STRIDE 80            // (32+8)*2 bytes per m-row
#define B_STRIDE 272           // (128+8)*2 bytes per k-row
#define A_TILE (128 * A_STRIDE)        // 10240
#define B_TILE (KCH * B_STRIDE)        // 8704
#define OFF_A  0
#define OFF_B  A_TILE
#define STAGE_SZ (A_TILE + B_TILE)         // 18944
#define NSTAGE 5
#define SMEM_MMA (NSTAGE * STAGE_SZ)       // 94720 (x2 CTAs = 189440 < 227KB)

// MODE 0: GEMM1 (A = gathered x fp16, epilogue tanh -> g_h16)
// MODE 1: GEMM2 (A = contiguous h rows, epilogue weighted store -> g_y)
template <int KDIM, int NDIM, int MODE>
__global__ __launch_bounds__(256, 2) void k_moe_mma(const float* __restrict__ bias)
{
    int e = blockIdx.z;
    int rows = g_counts[e];
    int base = g_starts[e];
    int row0 = blockIdx.y * 128;
    if (row0 >= rows) return;
    int col0 = blockIdx.x * 128;

    extern __shared__ char smem[];
    uint32_t sb = smem_to_u32(smem);
    int tid = threadIdx.x, wid = tid >> 5, lane = tid & 31;

    // ---- global load mapping ----
    int am_row = tid >> 1, a_hf = tid & 1;   // A: 2 threads/row, 1 x 16B each half
    int bk_row = tid >> 3, b_sg = tid & 7;   // B: 8 threads/k-row, 2 x 16B

    const __half* AP;
    size_t aoff;
    int arc = (row0 + am_row < rows) ? (row0 + am_row) : (rows - 1);
    if (MODE == 0) {
        AP = g_x16;
        aoff = (size_t)g_rowmap[base + arc] * KDIM;
    } else {
        AP = g_h16;
        aoff = (size_t)(base + arc) * KDIM;
    }
    const __half* BP = (MODE == 0 ? g_w1 : g_w2) + (size_t)e * KDIM * NDIM;

    uint32_t sA = sb + am_row * A_STRIDE + a_hf * 32;
    uint32_t sB = sb + bk_row * B_STRIDE + b_sg * 32;

    auto load_chunk = [&](int stage, int kc) {
        uint32_t bb = stage * STAGE_SZ;
        const __half* ga = AP + aoff + kc * KCH + a_hf * 16;
        CP_ASYNC16(sA + bb + OFF_A, ga);
        CP_ASYNC16(sA + bb + OFF_A + 16, ga + 8);
        const __half* gb = BP + (size_t)(kc * KCH + bk_row) * NDIM + col0 + b_sg * 16;
        CP_ASYNC16(sB + bb + OFF_B, gb);
        CP_ASYNC16(sB + bb + OFF_B + 16, gb + 8);
        CP_COMMIT();
    };

    // ---- ldmatrix fragment addresses (warp tile 64M x 32N; 8 warps = 2M x 4N) ----
    int warp_m = wid & 1, warp_n = wid >> 1;
    int a_row_l = (lane & 7) + ((lane >> 3) & 1) * 8;
    int a_k_l   = ((lane >> 4) & 1) * 8;
    uint32_t aAddr0 = sb + (warp_m * 64 + a_row_l) * A_STRIDE + a_k_l * 2;
    uint32_t bAddr0 = sb + (lane & 15) * B_STRIDE + warp_n * 64;   // 32 n * 2B

    float acc[4][4][4];
#pragma unroll
    for (int mf = 0; mf < 4; mf++)
#pragma unroll
        for (int nf = 0; nf < 4; nf++)
#pragma unroll
            for (int q = 0; q < 4; q++) acc[mf][nf][q] = 0.f;

    const int NK = KDIM / KCH;
    load_chunk(0, 0);
    load_chunk(1, 1);
    load_chunk(2, 2);
    load_chunk(3, 3);

    for (int kc = 0; kc < NK; kc++) {
        int rem = NK - 1 - kc;
        if (rem >= 3)      CP_WAIT(3);
        else if (rem == 2) CP_WAIT(2);
        else if (rem == 1) CP_WAIT(1);
        else               CP_WAIT(0);
        __syncthreads();
        uint32_t bb = (kc % NSTAGE) * STAGE_SZ;
#pragma unroll
        for (int ks = 0; ks < 2; ks++) {
            uint32_t a_r[4][4];
#pragma unroll
            for (int mf = 0; mf < 4; mf++) {
                uint32_t ad = aAddr0 + bb + mf * 16 * A_STRIDE + ks * 32;
                LDMATRIX_X4(a_r[mf][0], a_r[mf][1], a_r[mf][2], a_r[mf][3], ad + OFF_A);
            }
#pragma unroll
            for (int nf = 0; nf < 4; nf++) {
                uint32_t bd = bAddr0 + bb + ks * 16 * B_STRIDE + nf * 16;
                uint32_t b_r[2];
                LDMATRIX_X2T(b_r[0], b_r[1], bd + OFF_B);
#pragma unroll
                for (int mf = 0; mf < 4; mf++)
                    MMA16816(acc[mf][nf], a_r[mf], b_r);
            }
        }
        __syncthreads();
        if (kc + 4 < NK) load_chunk((kc + 4) % NSTAGE, kc + 4);
    }

    // ---- epilogue (register accumulators) ----
    int rb = row0 + warp_m * 64 + (lane >> 2);
    int cb = col0 + warp_n * 32 + (lane & 3) * 2;
    const float* bp = bias + (size_t)e * NDIM;
#pragma unroll
    for (int mf = 0; mf < 4; mf++) {
#pragma unroll
        for (int half2 = 0; half2 < 2; half2++) {
            int r = rb + mf * 16 + half2 * 8;
            if (r >= rows) continue;
            int pos = base + r;
            size_t orow = (size_t)pos * NDIM;
            float wgt = (MODE == 1) ? g_roww[pos] : 1.f;
#pragma unroll
            for (int nf = 0; nf < 4; nf++) {
                int c = cb + nf * 8;
                float v0 = acc[mf][nf][half2 * 2 + 0] + bp[c];
                float v1 = acc[mf][nf][half2 * 2 + 1] + bp[c + 1];
                if (MODE == 0) {
                    __half t0 = __float2half(tanhf(v0));
                    __half t1 = __float2half(tanhf(v1));
                    uint32_t ph = ((uint32_t)__half_as_ushort(t1) << 16) | __half_as_ushort(t0);
                    *(uint32_t*)(g_h16 + orow + c) = ph;
                } else {
                    float2 w;
                    w.x = v0 * wgt;
                    w.y = v1 * wgt;
                    *(float2*)(g_y + orow + c) = w;
                }
            }
        }
    }
}

// ------------------------- launch -------------------------
extern "C" void kernel_launch(void* const* d_in, const int* in_sizes, int n_in,
                              void* d_out, int out_size)
{
    const float* x   = (const float*)d_in[0];
    const float* gw1 = (const float*)d_in[1];
    const float* gb1 = (const float*)d_in[2];
    const float* gw2 = (const float*)d_in[3];
    const float* gb2 = (const float*)d_in[4];
    const float* ew1 = (const float*)d_in[5];
    const float* eb1 = (const float*)d_in[6];
    const float* ew2 = (const float*)d_in[7];
    const float* eb2 = (const float*)d_in[8];
    float* out = (float*)d_out;

    cudaFuncSetAttribute(k_moe_mma<DM, HE, 0>, cudaFuncAttributeMaxDynamicSharedMemorySize, SMEM_MMA);
    cudaFuncSetAttribute(k_moe_mma<HE, DM, 1>, cudaFuncAttributeMaxDynamicSharedMemorySize, SMEM_MMA);

    cudaMemsetAsync(d_out, 0, (size_t)out_size * sizeof(float));
    k_init<<<1, 32>>>();

    // precision conversions
    k_xsplit<<<(BT * DM) / 1024, 256>>>(x);
    k_wconv<0><<<(NE * DM * HE) / 1024, 256>>>(ew1);
    k_wconv<1><<<(NE * HE * DM) / 1024, 256>>>(ew2);

    // gating
    dim3 gg(GHD / 128, BT / 128);
    k_gate_gemm<<<gg, 256>>>(x, gw1, gb1);
    long long extra = (long long)out_size - (long long)BT * DM;
    float* tail = (extra >= (long long)BT * TK) ? (out + (size_t)BT * DM) : nullptr;
    k_gate2<<<BT / 8, 256>>>(gw2, gb2, tail);
    k_scan<<<1, 1>>>();
    k_scatter<<<BT / 256, 256>>>();

    // expert GEMMs (pure fp16 HMMA, KCH=32, 5-stage, 2 CTAs/SM)
    dim3 ge1(HE / 128, MAXROWS_PER_E / 128, NE);
    k_moe_mma<DM, HE, 0><<<ge1, 256, SMEM_MMA>>>(eb1);
    dim3 ge2(DM / 128, MAXROWS_PER_E / 128, NE);
    k_moe_mma<HE, DM, 1><<<ge2, 256, SMEM_MMA>>>(eb2);

    // combine: out[t] = y[pos0] + y[pos1]
    k_combine<<<(BT * DM / 4) / 256, 256>>>(out);
}

// round 16
// speedup vs baseline: 1.1037x; 1.0540x over previous
#include <cuda_runtime.h>
#include <cuda_fp16.h>
#include <math.h>
#include <stdint.h>

// MedicalMoE on GB300 (plain sm_103 target).
// Round 16: gate GEMM1 moved to tensor cores with 3-term fp16 compensation
// (xh*wh + xh*wl + xl*wh, fp32 accum; dropped term ~2^-22 == fp32-rounding
// order, so top-2 selection risk is unchanged). Experts: round-15 engine.
#define BT 16384
#define DM 1024
#define HE 4096
#define NE 8
#define TK 2
#define GHD 256
#define NROWS (BT * TK)
#define MAXROWS_PER_E BT

// ------------------------- device scratch -------------------------
__device__ float g_hidden[(size_t)BT * GHD];
__device__ int   g_counts[NE];
__device__ int   g_starts[NE];
__device__ int   g_fill[NE];
__device__ int   g_eid[NROWS];
__device__ float g_ew[NROWS];
__device__ int   g_rowmap[NROWS];
__device__ float g_roww[NROWS];
__device__ int   g_postok[NROWS];
__device__ __half g_x16[(size_t)BT * DM];      // x hi
__device__ __half g_xl16[(size_t)BT * DM];     // x lo (gate only)
__device__ __half g_gw1h[(size_t)DM * GHD], g_gw1l[(size_t)DM * GHD]; // gate W1 hi/lo [K][N]
__device__ __half g_w1[(size_t)NE * DM * HE];  // [E][K][N] fp16
__device__ __half g_w2[(size_t)NE * HE * DM];  // [E][K][N] fp16
__device__ __half g_h16[(size_t)NROWS * HE];
__device__ float  g_y[(size_t)NROWS * DM];

// ------------------------- PTX helpers -------------------------
__device__ __forceinline__ uint32_t smem_to_u32(const void* p) {
    uint32_t a;
    asm("{ .reg .u64 t; cvta.to.shared.u64 t, %1; cvt.u32.u64 %0, t; }" : "=r"(a) : "l"(p));
    return a;
}
#define CP_ASYNC16(saddr, gptr) \
    asm volatile("cp.async.cg.shared.global [%0], [%1], 16;" :: "r"(saddr), "l"(gptr) : "memory")
#define CP_COMMIT() asm volatile("cp.async.commit_group;" ::: "memory")
#define CP_WAIT(n)  asm volatile("cp.async.wait_group %0;" :: "n"(n) : "memory")
#define LDMATRIX_X4(r0,r1,r2,r3, addr) \
    asm volatile("ldmatrix.sync.aligned.m8n8.x4.shared.b16 {%0,%1,%2,%3}, [%4];" \
        : "=r"(r0),"=r"(r1),"=r"(r2),"=r"(r3) : "r"(addr) : "memory")
#define LDMATRIX_X2T(r0,r1, addr) \
    asm volatile("ldmatrix.sync.aligned.m8n8.x2.trans.shared.b16 {%0,%1}, [%2];" \
        : "=r"(r0),"=r"(r1) : "r"(addr) : "memory")
#define MMA16816(d, a, b) \
    asm volatile("mma.sync.aligned.m16n8k16.row.col.f32.f16.f16.f32 " \
        "{%0,%1,%2,%3}, {%4,%5,%6,%7}, {%8,%9}, {%0,%1,%2,%3};" \
        : "+f"((d)[0]),"+f"((d)[1]),"+f"((d)[2]),"+f"((d)[3]) \
        : "r"((a)[0]),"r"((a)[1]),"r"((a)[2]),"r"((a)[3]),"r"((b)[0]),"r"((b)[1]))

// ------------------------- setup kernels -------------------------
__global__ void k_init() { if (threadIdx.x < NE) g_counts[threadIdx.x] = 0; }

__global__ void k_scan() {
    int s = 0;
    for (int e = 0; e < NE; e++) { g_starts[e] = s; s += g_counts[e]; g_fill[e] = 0; }
}

__global__ void k_scatter() {
    int t = blockIdx.x * blockDim.x + threadIdx.x;
    if (t >= BT) return;
#pragma unroll
    for (int k = 0; k < TK; k++) {
        int e = g_eid[t * TK + k];
        int pos = g_starts[e] + atomicAdd(&g_fill[e], 1);
        g_rowmap[pos] = t;
        g_roww[pos] = g_ew[t * TK + k];
        g_postok[t * TK + k] = pos;
    }
}

__global__ __launch_bounds__(256) void k_combine(float* __restrict__ out)
{
    size_t i = (size_t)blockIdx.x * 256 + threadIdx.x;
    int t = (int)(i / (DM / 4));
    int off = (int)(i % (DM / 4)) * 4;
    int p0 = g_postok[t * TK + 0];
    int p1 = g_postok[t * TK + 1];
    float4 a = *(const float4*)(g_y + (size_t)p0 * DM + off);
    float4 b = *(const float4*)(g_y + (size_t)p1 * DM + off);
    float4 r;
    r.x = a.x + b.x; r.y = a.y + b.y; r.z = a.z + b.z; r.w = a.w + b.w;
    *(float4*)(out + (size_t)t * DM + off) = r;
}

// x -> fp16 hi + lo
__global__ __launch_bounds__(256) void k_xsplit(const float* __restrict__ x) {
    size_t i = ((size_t)blockIdx.x * 256 + threadIdx.x) * 4;
    float4 v = *(const float4*)(x + i);
    __half h0 = __float2half(v.x), h1 = __float2half(v.y);
    __half h2 = __float2half(v.z), h3 = __float2half(v.w);
    __half l0 = __float2half(v.x - __half2float(h0));
    __half l1 = __float2half(v.y - __half2float(h1));
    __half l2 = __float2half(v.z - __half2float(h2));
    __half l3 = __float2half(v.w - __half2float(h3));
    uint2 ph, pl;
    ph.x = ((uint32_t)__half_as_ushort(h1) << 16) | __half_as_ushort(h0);
    ph.y = ((uint32_t)__half_as_ushort(h3) << 16) | __half_as_ushort(h2);
    pl.x = ((uint32_t)__half_as_ushort(l1) << 16) | __half_as_ushort(l0);
    pl.y = ((uint32_t)__half_as_ushort(l3) << 16) | __half_as_ushort(l2);
    *(uint2*)(g_x16 + i) = ph;
    *(uint2*)(g_xl16 + i) = pl;
}

// gate W1 -> fp16 hi/lo (DM*GHD elems)
__global__ __launch_bounds__(256) void k_gw1split(const float* __restrict__ W)
{
    size_t i = ((size_t)blockIdx.x * 256 + threadIdx.x) * 4;
    float4 v = *(const float4*)(W + i);
    __half h0 = __float2half(v.x), h1 = __float2half(v.y);
    __half h2 = __float2half(v.z), h3 = __float2half(v.w);
    __half l0 = __float2half(v.x - __half2float(h0));
    __half l1 = __float2half(v.y - __half2float(h1));
    __half l2 = __float2half(v.z - __half2float(h2));
    __half l3 = __float2half(v.w - __half2float(h3));
    uint2 ph, pl;
    ph.x = ((uint32_t)__half_as_ushort(h1) << 16) | __half_as_ushort(h0);
    ph.y = ((uint32_t)__half_as_ushort(h3) << 16) | __half_as_ushort(h2);
    pl.x = ((uint32_t)__half_as_ushort(l1) << 16) | __half_as_ushort(l0);
    pl.y = ((uint32_t)__half_as_ushort(l3) << 16) | __half_as_ushort(l2);
    *(uint2*)(g_gw1h + i) = ph;
    *(uint2*)(g_gw1l + i) = pl;
}

// expert weights -> fp16
template <int W2>
__global__ __launch_bounds__(256) void k_wconv(const float* __restrict__ W)
{
    size_t i = ((size_t)blockIdx.x * 256 + threadIdx.x) * 4;
    float4 v = *(const float4*)(W + i);
    __half h0 = __float2half(v.x), h1 = __float2half(v.y);
    __half h2 = __float2half(v.z), h3 = __float2half(v.w);
    uint2 p;
    p.x = ((uint32_t)__half_as_ushort(h1) << 16) | __half_as_ushort(h0);
    p.y = ((uint32_t)__half_as_ushort(h3) << 16) | __half_as_ushort(h2);
    if (W2) *(uint2*)(g_w2 + i) = p;
    else    *(uint2*)(g_w1 + i) = p;
}

// ------------------------- gate GEMM1 on tensor cores (3-term fp16) -----------
// hidden = relu(x @ gw1 + gb1), CTA tile 128M x 128N, KCH 32, 3-stage.
#define GA_STRIDE 80
#define GB_STRIDE 272
#define GA_TILE (128 * GA_STRIDE)      // 10240
#define GB_TILE (32 * GB_STRIDE)       // 8704
#define GOFF_AH 0
#define GOFF_AL GA_TILE
#define GOFF_BH (2 * GA_TILE)
#define GOFF_BL (2 * GA_TILE + GB_TILE)
#define GSTAGE_SZ (2 * GA_TILE + 2 * GB_TILE)   // 37888
#define GNSTAGE 3
#define SMEM_GATE (GNSTAGE * GSTAGE_SZ)         // 113664 (x2 = 227328 <= 228KB)

__global__ __launch_bounds__(256, 2) void k_gate_mma(const float* __restrict__ bias)
{
    int row0 = blockIdx.y * 128;
    int col0 = blockIdx.x * 128;

    extern __shared__ char smem[];
    uint32_t sb = smem_to_u32(smem);
    int tid = threadIdx.x, wid = tid >> 5, lane = tid & 31;

    int am_row = tid >> 1, a_hf = tid & 1;
    int bk_row = tid >> 3, b_sg = tid & 7;

    size_t aoff = (size_t)(row0 + am_row) * DM;
    uint32_t sA = sb + am_row * GA_STRIDE + a_hf * 32;
    uint32_t sB = sb + bk_row * GB_STRIDE + b_sg * 32;

    auto load_chunk = [&](int stage, int kc) {
        uint32_t bb = stage * GSTAGE_SZ;
        const __half* gah = g_x16 + aoff + kc * 32 + a_hf * 16;
        const __half* gal = g_xl16 + aoff + kc * 32 + a_hf * 16;
        CP_ASYNC16(sA + bb + GOFF_AH, gah);
        CP_ASYNC16(sA + bb + GOFF_AH + 16, gah + 8);
        CP_ASYNC16(sA + bb + GOFF_AL, gal);
        CP_ASYNC16(sA + bb + GOFF_AL + 16, gal + 8);
        const __half* gbh = g_gw1h + (size_t)(kc * 32 + bk_row) * GHD + col0 + b_sg * 16;
        const __half* gbl = g_gw1l + (size_t)(kc * 32 + bk_row) * GHD + col0 + b_sg * 16;
        CP_ASYNC16(sB + bb + GOFF_BH, gbh);
        CP_ASYNC16(sB + bb + GOFF_BH + 16, gbh + 8);
        CP_ASYNC16(sB + bb + GOFF_BL, gbl);
        CP_ASYNC16(sB + bb + GOFF_BL + 16, gbl + 8);
        CP_COMMIT();
    };

    int warp_m = wid & 1, warp_n = wid >> 1;
    int a_row_l = (lane & 7) + ((lane >> 3) & 1) * 8;
    int a_k_l   = ((lane >> 4) & 1) * 8;
    uint32_t aAddr0 = sb + (warp_m * 64 + a_row_l) * GA_STRIDE + a_k_l * 2;
    uint32_t bAddr0 = sb + (lane & 15) * GB_STRIDE + warp_n * 64;

    float acc[4][4][4];
#pragma unroll
    for (int mf = 0; mf < 4; mf++)
#pragma unroll
        for (int nf = 0; nf < 4; nf++)
#pragma unroll
            for (int q = 0; q < 4; q++) acc[mf][nf][q] = 0.f;

    const int NK = DM / 32;
    load_chunk(0, 0);
    load_chunk(1, 1);

    for (int kc = 0; kc < NK; kc++) {
        if (kc + 1 < NK) CP_WAIT(1); else CP_WAIT(0);
        __syncthreads();
        uint32_t bb = (kc % GNSTAGE) * GSTAGE_SZ;
#pragma unroll
        for (int ks = 0; ks < 2; ks++) {
            uint32_t a_h[4][4], a_l[4][4];
#pragma unroll
            for (int mf = 0; mf < 4; mf++) {
                uint32_t ad = aAddr0 + bb + mf * 16 * GA_STRIDE + ks * 32;
                LDMATRIX_X4(a_h[mf][0], a_h[mf][1], a_h[mf][2], a_h[mf][3], ad + GOFF_AH);
                LDMATRIX_X4(a_l[mf][0], a_l[mf][1], a_l[mf][2], a_l[mf][3], ad + GOFF_AL);
            }
#pragma unroll
            for (int nf = 0; nf < 4; nf++) {
                uint32_t bd = bAddr0 + bb + ks * 16 * GB_STRIDE + nf * 16;
                uint32_t b_h[2], b_l[2];
                LDMATRIX_X2T(b_h[0], b_h[1], bd + GOFF_BH);
                LDMATRIX_X2T(b_l[0], b_l[1], bd + GOFF_BL);
#pragma unroll
                for (int mf = 0; mf < 4; mf++) {
                    MMA16816(acc[mf][nf], a_h[mf], b_h);
                    MMA16816(acc[mf][nf], a_h[mf], b_l);
                    MMA16816(acc[mf][nf], a_l[mf], b_h);
                }
            }
        }
        __syncthreads();
        if (kc + 2 < NK) load_chunk((kc + 2) % GNSTAGE, kc + 2);
    }

    // epilogue: relu(acc + b) -> fp32 g_hidden [BT][GHD]
    int rb = row0 + warp_m * 64 + (lane >> 2);
    int cb = col0 + warp_n * 32 + (lane & 3) * 2;
#pragma unroll
    for (int mf = 0; mf < 4; mf++) {
#pragma unroll
        for (int half2 = 0; half2 < 2; half2++) {
            int r = rb + mf * 16 + half2 * 8;
            size_t orow = (size_t)r * GHD;
#pragma unroll
            for (int nf = 0; nf < 4; nf++) {
                int c = cb + nf * 8;
                float v0 = acc[mf][nf][half2 * 2 + 0] + bias[c];
                float v1 = acc[mf][nf][half2 * 2 + 1] + bias[c + 1];
                float2 w;
                w.x = v0 > 0.f ? v0 : 0.f;
                w.y = v1 > 0.f ? v1 : 0.f;
                *(float2*)(g_hidden + orow + c) = w;
            }
        }
    }
}

// ------------------------- gate head (fp32, proven) -------------------------
__global__ __launch_bounds__(256) void k_gate2(
    const float* __restrict__ gw2, const float* __restrict__ gb2, float* tail)
{
    __shared__ float sW[GHD * NE];
    __shared__ float sb[NE];
    int tid = threadIdx.x;
    for (int i = tid; i < GHD * NE; i += 256) sW[i] = gw2[i];
    if (tid < NE) sb[tid] = gb2[tid];
    __syncthreads();
    int warp = tid >> 5, lane = tid & 31;
    int token = blockIdx.x * 8 + warp;
    const float* hrow = g_hidden + (size_t)token * GHD;
    float l[NE];
#pragma unroll
    for (int e = 0; e < NE; e++) l[e] = 0.f;
#pragma unroll
    for (int i = 0; i < GHD / 32; i++) {
        int r = lane + i * 32;
        float hv = hrow[r];
#pragma unroll
        for (int e = 0; e < NE; e++) l[e] += hv * sW[r * NE + e];
    }
#pragma unroll
    for (int off = 16; off > 0; off >>= 1)
#pragma unroll
        for (int e = 0; e < NE; e++) l[e] += __shfl_down_sync(0xffffffffu, l[e], off);
    if (lane == 0) {
        float p[NE]; float m = -1e30f;
#pragma unroll
        for (int e = 0; e < NE; e++) { l[e] += sb[e]; m = fmaxf(m, l[e]); }
        float s = 0.f;
#pragma unroll
        for (int e = 0; e < NE; e++) { p[e] = expf(l[e] - m); s += p[e]; }
        float inv = 1.f / s;
#pragma unroll
        for (int e = 0; e < NE; e++) p[e] *= inv;
        int b0 = 0; float v0 = p[0];
#pragma unroll
        for (int e = 1; e < NE; e++) if (p[e] > v0) { v0 = p[e]; b0 = e; }
        int b1 = -1; float v1 = -1e30f;
#pragma unroll
        for (int e = 0; e < NE; e++) if (e != b0 && p[e] > v1) { v1 = p[e]; b1 = e; }
        float d = 1.f / (v0 + v1);
        g_eid[token * TK + 0] = b0; g_ew[token * TK + 0] = v0 * d;
        g_eid[token * TK + 1] = b1; g_ew[token * TK + 1] = v1 * d;
        atomicAdd(&g_counts[b0], 1);
        atomicAdd(&g_counts[b1], 1);
        if (tail) { tail[token * TK + 0] = (float)b0; tail[token * TK + 1] = (float)b1; }
    }
}

// ------------------------- pure fp16 mma.sync grouped GEMM (round-15 engine) ------
#define KCH 32
#define A_STRIDE 80
#define B_STRIDE 272
#define A_TILE (128 * A_STRIDE)
#define B_TILE (KCH * B_STRIDE)
#define OFF_A  0
#define OFF_B  A_TILE
#define STAGE_SZ (A_TILE + B_TILE)
#define NSTAGE 5
#define SMEM_MMA (NSTAGE * STAGE_SZ)

template <int KDIM, int NDIM, int MODE>
__global__ __launch_bounds__(256, 2) void k_moe_mma(const float* __restrict__ bias)
{
    int e = blockIdx.z;
    int rows = g_counts[e];
    int base = g_starts[e];
    int row0 = blockIdx.y * 128;
    if (row0 >= rows) return;
    int col0 = blockIdx.x * 128;

    extern __shared__ char smem[];
    uint32_t sb = smem_to_u32(smem);
    int tid = threadIdx.x, wid = tid >> 5, lane = tid & 31;

    int am_row = tid >> 1, a_hf = tid & 1;
    int bk_row = tid >> 3, b_sg = tid & 7;

    const __half* AP;
    size_t aoff;
    int arc = (row0 + am_row < rows) ? (row0 + am_row) : (rows - 1);
    if (MODE == 0) {
        AP = g_x16;
        aoff = (size_t)g_rowmap[base + arc] * KDIM;
    } else {
        AP = g_h16;
        aoff = (size_t)(base + arc) * KDIM;
    }
    const __half* BP = (MODE == 0 ? g_w1 : g_w2) + (size_t)e * KDIM * NDIM;

    uint32_t sA = sb + am_row * A_STRIDE + a_hf * 32;
    uint32_t sB = sb + bk_row * B_STRIDE + b_sg * 32;

    auto load_chunk = [&](int stage, int kc) {
        uint32_t bb = stage * STAGE_SZ;
        const __half* ga = AP + aoff + kc * KCH + a_hf * 16;
        CP_ASYNC16(sA + bb + OFF_A, ga);
        CP_ASYNC16(sA + bb + OFF_A + 16, ga + 8);
        const __half* gb = BP + (size_t)(kc * KCH + bk_row) * NDIM + col0 + b_sg * 16;
        CP_ASYNC16(sB + bb + OFF_B, gb);
        CP_ASYNC16(sB + bb + OFF_B + 16, gb + 8);
        CP_COMMIT();
    };

    int warp_m = wid & 1, warp_n = wid >> 1;
    int a_row_l = (lane & 7) + ((lane >> 3) & 1) * 8;
    int a_k_l   = ((lane >> 4) & 1) * 8;
    uint32_t aAddr0 = sb + (warp_m * 64 + a_row_l) * A_STRIDE + a_k_l * 2;
    uint32_t bAddr0 = sb + (lane & 15) * B_STRIDE + warp_n * 64;

    float acc[4][4][4];
#pragma unroll
    for (int mf = 0; mf < 4; mf++)
#pragma unroll
        for (int nf = 0; nf < 4; nf++)
#pragma unroll
            for (int q = 0; q < 4; q++) acc[mf][nf][q] = 0.f;

    const int NK = KDIM / KCH;
    load_chunk(0, 0);
    load_chunk(1, 1);
    load_chunk(2, 2);
    load_chunk(3, 3);

    for (int kc = 0; kc < NK; kc++) {
        int rem = NK - 1 - kc;
        if (rem >= 3)      CP_WAIT(3);
        else if (rem == 2) CP_WAIT(2);
        else if (rem == 1) CP_WAIT(1);
        else               CP_WAIT(0);
        __syncthreads();
        uint32_t bb = (kc % NSTAGE) * STAGE_SZ;
#pragma unroll
        for (int ks = 0; ks < 2; ks++) {
            uint32_t a_r[4][4];
#pragma unroll
            for (int mf = 0; mf < 4; mf++) {
                uint32_t ad = aAddr0 + bb + mf * 16 * A_STRIDE + ks * 32;
                LDMATRIX_X4(a_r[mf][0], a_r[mf][1], a_r[mf][2], a_r[mf][3], ad + OFF_A);
            }
#pragma unroll
            for (int nf = 0; nf < 4; nf++) {
                uint32_t bd = bAddr0 + bb + ks * 16 * B_STRIDE + nf * 16;
                uint32_t b_r[2];
                LDMATRIX_X2T(b_r[0], b_r[1], bd + OFF_B);
#pragma unroll
                for (int mf = 0; mf < 4; mf++)
                    MMA16816(acc[mf][nf], a_r[mf], b_r);
            }
        }
        __syncthreads();
        if (kc + 4 < NK) load_chunk((kc + 4) % NSTAGE, kc + 4);
    }

    int rb = row0 + warp_m * 64 + (lane >> 2);
    int cb = col0 + warp_n * 32 + (lane & 3) * 2;
    const float* bp = bias + (size_t)e * NDIM;
#pragma unroll
    for (int mf = 0; mf < 4; mf++) {
#pragma unroll
        for (int half2 = 0; half2 < 2; half2++) {
            int r = rb + mf * 16 + half2 * 8;
            if (r >= rows) continue;
            int pos = base + r;
            size_t orow = (size_t)pos * NDIM;
            float wgt = (MODE == 1) ? g_roww[pos] : 1.f;
#pragma unroll
            for (int nf = 0; nf < 4; nf++) {
                int c = cb + nf * 8;
                float v0 = acc[mf][nf][half2 * 2 + 0] + bp[c];
                float v1 = acc[mf][nf][half2 * 2 + 1] + bp[c + 1];
                if (MODE == 0) {
                    __half t0 = __float2half(tanhf(v0));
                    __half t1 = __float2half(tanhf(v1));
                    uint32_t ph = ((uint32_t)__half_as_ushort(t1) << 16) | __half_as_ushort(t0);
                    *(uint32_t*)(g_h16 + orow + c) = ph;
                } else {
                    float2 w;
                    w.x = v0 * wgt;
                    w.y = v1 * wgt;
                    *(float2*)(g_y + orow + c) = w;
                }
            }
        }
    }
}

// ------------------------- launch -------------------------
extern "C" void kernel_launch(void* const* d_in, const int* in_sizes, int n_in,
                              void* d_out, int out_size)
{
    const float* x   = (const float*)d_in[0];
    const float* gw1 = (const float*)d_in[1];
    const float* gb1 = (const float*)d_in[2];
    const float* gw2 = (const float*)d_in[3];
    const float* gb2 = (const float*)d_in[4];
    const float* ew1 = (const float*)d_in[5];
    const float* eb1 = (const float*)d_in[6];
    const float* ew2 = (const float*)d_in[7];
    const float* eb2 = (const float*)d_in[8];
    float* out = (float*)d_out;

    cudaFuncSetAttribute(k_gate_mma, cudaFuncAttributeMaxDynamicSharedMemorySize, SMEM_GATE);
    cudaFuncSetAttribute(k_moe_mma<DM, HE, 0>, cudaFuncAttributeMaxDynamicSharedMemorySize, SMEM_MMA);
    cudaFuncSetAttribute(k_moe_mma<HE, DM, 1>, cudaFuncAttributeMaxDynamicSharedMemorySize, SMEM_MMA);

    cudaMemsetAsync(d_out, 0, (size_t)out_size * sizeof(float));
    k_init<<<1, 32>>>();

    // precision conversions
    k_xsplit<<<(BT * DM) / 1024, 256>>>(x);
    k_gw1split<<<(DM * GHD) / 1024, 256>>>(gw1);
    k_wconv<0><<<(NE * DM * HE) / 1024, 256>>>(ew1);
    k_wconv<1><<<(NE * HE * DM) / 1024, 256>>>(ew2);

    // gating (tensor-core GEMM1 + fp32 head)
    dim3 gg(GHD / 128, BT / 128);
    k_gate_mma<<<gg, 256, SMEM_GATE>>>(gb1);
    long long extra = (long long)out_size - (long long)BT * DM;
    float* tail = (extra >= (long long)BT * TK) ? (out + (size_t)BT * DM) : nullptr;
    k_gate2<<<BT / 8, 256>>>(gw2, gb2, tail);
    k_scan<<<1, 1>>>();
    k_scatter<<<BT / 256, 256>>>();

    // expert GEMMs (pure fp16 HMMA, KCH=32, 5-stage, 2 CTAs/SM)
    dim3 ge1(HE / 128, MAXROWS_PER_E / 128, NE);
    k_moe_mma<DM, HE, 0><<<ge1, 256, SMEM_MMA>>>(eb1);
    dim3 ge2(DM / 128, MAXROWS_PER_E / 128, NE);
    k_moe_mma<HE, DM, 1><<<ge2, 256, SMEM_MMA>>>(eb2);

    // combine: out[t] = y[pos0] + y[pos1]
    k_combine<<<(BT * DM / 4) / 256, 256>>>(out);
}